// round 5
// baseline (speedup 1.0000x reference)
#include <cuda_runtime.h>
#include <math.h>

#define BATCH 64
#define SEQ   512
#define EMBD  256
#define HIDD  512
#define GATES 2048      // 4*HIDD
#define WROW  768       // EMB + HID
#define NCLS  50257
#define RCTAS 128       // persistent recurrence CTAs (<=148 -> co-resident)

// ---------------- device-global scratch (no runtime allocation allowed) ----
__device__ float g_xproj[(size_t)SEQ * GATES * BATCH];   // [t][g][b]
__device__ float g_h[2][BATCH * HIDD];                   // double-buffered h [b][k]
__device__ float g_C[HIDD * BATCH];                      // cell state, idx=j*64+b
__device__ float g_part[4][GATES * BATCH];               // K-split partials [kc][g][b]
__device__ int   g_pflag[RCTAS];                         // partials-ready wave (== t+1)
__device__ int   g_hflag[RCTAS];                         // h-ready wave (== t+1)

// ---------------- init ----------------
__global__ void k_init() {
    int i = blockIdx.x * 256 + threadIdx.x;
    if (i < BATCH * HIDD) {
        g_h[0][i] = 0.0f;
        g_C[i]    = 0.0f;
    }
    if (i < RCTAS) { g_pflag[i] = 0; g_hflag[i] = 0; }
}

// ---------------- Kernel 1: Xproj[t][g][b] = emb[x[b,t]] . Wx[g] + bias[g] --
__global__ __launch_bounds__(256) void k_xproj(const int* __restrict__ x,
                                               const float* __restrict__ emb,
                                               const float* __restrict__ W,
                                               const float* __restrict__ Wb) {
    const int t  = blockIdx.y;
    const int g0 = blockIdx.x * 64;

    __shared__ float a_s[64][20];   // [b][k]
    __shared__ float w_s[64][20];   // [g][k]
    __shared__ int   tok[64];

    const int tid = threadIdx.x;
    if (tid < 64) tok[tid] = x[tid * SEQ + t];
    __syncthreads();

    const int tx = tid & 15;   // -> b group
    const int ty = tid >> 4;   // -> g group

    float acc[4][4];            // [gi][bi]
#pragma unroll
    for (int i = 0; i < 4; i++)
#pragma unroll
        for (int j = 0; j < 4; j++) acc[i][j] = 0.0f;

    const int lr = tid >> 2;          // row 0..63
    const int lk = (tid & 3) * 4;     // 0,4,8,12

    for (int k0 = 0; k0 < EMBD; k0 += 16) {
        float4 av = *(const float4*)&emb[(size_t)tok[lr] * EMBD + k0 + lk];
        float4 wv = *(const float4*)&W[(size_t)(g0 + lr) * WROW + k0 + lk];
        *(float4*)&a_s[lr][lk] = av;
        *(float4*)&w_s[lr][lk] = wv;
        __syncthreads();

#pragma unroll
        for (int k = 0; k < 16; k += 4) {
            float4 af[4], wf[4];
#pragma unroll
            for (int i = 0; i < 4; i++) af[i] = *(const float4*)&a_s[tx * 4 + i][k];
#pragma unroll
            for (int i = 0; i < 4; i++) wf[i] = *(const float4*)&w_s[ty * 4 + i][k];
#pragma unroll
            for (int gi = 0; gi < 4; gi++)
#pragma unroll
                for (int bi = 0; bi < 4; bi++) {
                    acc[gi][bi] += af[bi].x * wf[gi].x;
                    acc[gi][bi] += af[bi].y * wf[gi].y;
                    acc[gi][bi] += af[bi].z * wf[gi].z;
                    acc[gi][bi] += af[bi].w * wf[gi].w;
                }
        }
        __syncthreads();
    }

#pragma unroll
    for (int gi = 0; gi < 4; gi++) {
        int g = g0 + ty * 4 + gi;
        float bias = Wb[g];
        float4 v;
        v.x = acc[gi][0] + bias;
        v.y = acc[gi][1] + bias;
        v.z = acc[gi][2] + bias;
        v.w = acc[gi][3] + bias;
        *(float4*)&g_xproj[((size_t)t * GATES + g) * BATCH + tx * 4] = v;
    }
}

// ---------------- Kernel 2: persistent recurrence (flag-wave sync) ----------
// 128 CTAs: gt = bx&31 (64-gate tile), kc = bx>>5 (128-k chunk).
// Per step: wait h flags -> GEMM partials -> pflag -> wait 16 producer pflags
//           -> elementwise cell -> hflag. No atomics, flags are monotone waves.
__global__ __launch_bounds__(256) void k_recur(const float* __restrict__ W) {
    const int bx = blockIdx.x;
    const int gt = bx & 31;
    const int kc = bx >> 5;
    const int g0 = gt * 64;
    const int kbase = kc * 128;

    __shared__ float w_s[64][132];   // [g][k] resident Wh tile (64g x 128k)
    __shared__ float h_s[64][36];    // [b][k] 32-k stage

    const int tid = threadIdx.x;
    const int tx = tid & 15;         // -> b group
    const int ty = tid >> 4;         // -> g group

    // elementwise ownership: idx = bx*256 + tid -> (j, b)
    const int idx = bx * 256 + tid;
    const int ej  = idx >> 6;
    const int eb  = idx & 63;
    // producer flag this thread polls (tid<16): gt' = (bx>>4) + (tid&3)*8, kc' = tid>>2
    const int pfidx = (tid >> 2) * 32 + ((bx >> 4) + (tid & 3) * 8);

    // Preload Wh tile once: 2048 float4, 8 per thread
#pragma unroll
    for (int i = 0; i < 8; i++) {
        int lin = tid + i * 256;
        int r   = lin >> 5;
        int kq  = (lin & 31) * 4;
        *(float4*)&w_s[r][kq] =
            *(const float4*)&W[(size_t)(g0 + r) * WROW + EMBD + kbase + kq];
    }
    __syncthreads();

    volatile int* vpf = g_pflag;
    volatile int* vhf = g_hflag;

    for (int t = 0; t < SEQ; t++) {
        // ---- wait: h for step t ready (elem of step t-1 done everywhere) ----
        if (tid < RCTAS) {
            while (vhf[tid] < t) { }
        }
        __syncthreads();

        const float* __restrict__ h = g_h[t & 1];

        float acc[4][4];
#pragma unroll
        for (int i = 0; i < 4; i++)
#pragma unroll
            for (int j = 0; j < 4; j++) acc[i][j] = 0.0f;

        for (int kk = 0; kk < 128; kk += 32) {
#pragma unroll
            for (int i = 0; i < 2; i++) {
                int lin = tid + i * 256;
                int r   = lin >> 3;
                int kq  = (lin & 7) * 4;
                *(float4*)&h_s[r][kq] = *(const float4*)&h[r * HIDD + kbase + kk + kq];
            }
            __syncthreads();

#pragma unroll
            for (int k = 0; k < 32; k += 4) {
                float4 hf[4], wf[4];
#pragma unroll
                for (int i = 0; i < 4; i++) hf[i] = *(const float4*)&h_s[tx * 4 + i][k];
#pragma unroll
                for (int i = 0; i < 4; i++) wf[i] = *(const float4*)&w_s[ty * 4 + i][kk + k];
#pragma unroll
                for (int gi = 0; gi < 4; gi++)
#pragma unroll
                    for (int bi = 0; bi < 4; bi++) {
                        acc[gi][bi] += hf[bi].x * wf[gi].x;
                        acc[gi][bi] += hf[bi].y * wf[gi].y;
                        acc[gi][bi] += hf[bi].z * wf[gi].z;
                        acc[gi][bi] += hf[bi].w * wf[gi].w;
                    }
            }
            __syncthreads();
        }

#pragma unroll
        for (int gi = 0; gi < 4; gi++) {
            int g = g0 + ty * 4 + gi;
            float4 v;
            v.x = acc[gi][0]; v.y = acc[gi][1]; v.z = acc[gi][2]; v.w = acc[gi][3];
            *(float4*)&g_part[kc][g * BATCH + tx * 4] = v;
        }
        __threadfence();
        __syncthreads();
        if (tid == 0) g_pflag[bx] = t + 1;   // release partials

        // ---- prefetch step-local elem inputs while producers finish ----
        float xp[4];
#pragma unroll
        for (int q = 0; q < 4; q++)
            xp[q] = g_xproj[((size_t)t * GATES + (q * HIDD + ej)) * BATCH + eb];
        float Cold = g_C[idx];

        // ---- wait: the 16 producer CTAs of this CTA's gate rows ----
        if (tid < 16) {
            while (vpf[pfidx] < t + 1) { }
        }
        __syncthreads();

        // ---- elementwise LSTM cell ----
        {
            float v[4];
#pragma unroll
            for (int q = 0; q < 4; q++) {
                int g = q * HIDD + ej;
                float s = xp[q];
#pragma unroll
                for (int c = 0; c < 4; c++) s += g_part[c][g * BATCH + eb];
                v[q] = s;
            }

            float f  = 1.0f / (1.0f + expf(-v[0]));
            float ig = 1.0f / (1.0f + expf(-v[1]));
            float o  = 1.0f / (1.0f + expf(-v[2]));
            float ct = tanhf(v[3]);

            float C = f * Cold + ig * ct;
            g_C[idx] = C;
            g_h[(t + 1) & 1][eb * HIDD + ej] = o * tanhf(C);
        }
        __threadfence();
        __syncthreads();
        if (tid == 0) g_hflag[bx] = t + 1;   // release h for step t+1
    }
}

// ---------------- Kernel 4: FC head  out[b][n] = h[b].fc[n] + bias ----------
__global__ __launch_bounds__(256) void k_fc(const float* __restrict__ fcw,
                                            const float* __restrict__ fcb,
                                            float* __restrict__ out) {
    const int n0 = blockIdx.x * 64;
    const float* __restrict__ h = g_h[0];   // t=511 wrote buffer (512&1)=0

    __shared__ float h_s[64][68];   // [b][k]
    __shared__ float w_s[64][68];   // [n][k]

    const int tid = threadIdx.x;
    const int tx = tid & 15;        // -> n group
    const int ty = tid >> 4;        // -> b group

    float acc[4][4];                // [bi][ni]
#pragma unroll
    for (int i = 0; i < 4; i++)
#pragma unroll
        for (int j = 0; j < 4; j++) acc[i][j] = 0.0f;

    for (int k0 = 0; k0 < HIDD; k0 += 64) {
#pragma unroll
        for (int i = 0; i < 4; i++) {
            int lin = tid + i * 256;
            int r   = lin >> 4;
            int kq  = (lin & 15) * 4;
            *(float4*)&h_s[r][kq] = *(const float4*)&h[r * HIDD + k0 + kq];
            int n = n0 + r;
            float4 wv = make_float4(0.f, 0.f, 0.f, 0.f);
            if (n < NCLS) wv = *(const float4*)&fcw[(size_t)n * HIDD + k0 + kq];
            *(float4*)&w_s[r][kq] = wv;
        }
        __syncthreads();

#pragma unroll
        for (int k = 0; k < 64; k += 4) {
            float4 hf[4], wf[4];
#pragma unroll
            for (int i = 0; i < 4; i++) hf[i] = *(const float4*)&h_s[ty * 4 + i][k];
#pragma unroll
            for (int i = 0; i < 4; i++) wf[i] = *(const float4*)&w_s[tx * 4 + i][k];
#pragma unroll
            for (int bi = 0; bi < 4; bi++)
#pragma unroll
                for (int ni = 0; ni < 4; ni++) {
                    acc[bi][ni] += hf[bi].x * wf[ni].x;
                    acc[bi][ni] += hf[bi].y * wf[ni].y;
                    acc[bi][ni] += hf[bi].z * wf[ni].z;
                    acc[bi][ni] += hf[bi].w * wf[ni].w;
                }
        }
        __syncthreads();
    }

#pragma unroll
    for (int bi = 0; bi < 4; bi++) {
        int b = ty * 4 + bi;
#pragma unroll
        for (int ni = 0; ni < 4; ni++) {
            int n = n0 + tx * 4 + ni;
            if (n < NCLS) out[(size_t)b * NCLS + n] = acc[bi][ni] + fcb[n];
        }
    }
}

// ---------------- launch ----------------
extern "C" void kernel_launch(void* const* d_in, const int* in_sizes, int n_in,
                              void* d_out, int out_size) {
    const int*   x   = (const int*)  d_in[0];
    const float* emb = (const float*)d_in[1];
    const float* W   = (const float*)d_in[2];
    const float* Wb  = (const float*)d_in[3];
    const float* fcw = (const float*)d_in[4];
    const float* fcb = (const float*)d_in[5];
    float* out = (float*)d_out;

    k_init<<<(BATCH * HIDD + 255) / 256, 256>>>();
    k_xproj<<<dim3(32, SEQ), 256>>>(x, emb, W, Wb);
    k_recur<<<RCTAS, 256>>>(W);
    k_fc<<<(NCLS + 63) / 64, 256>>>(fcw, fcb, out);
}

// round 6
// speedup vs baseline: 2.5851x; 2.5851x over previous
#include <cuda_runtime.h>
#include <math.h>

#define BATCH 64
#define SEQ   512
#define EMBD  256
#define HIDD  512
#define GATES 2048      // 4*HIDD
#define WROW  768       // EMB + HID
#define NCLS  50257
#define RCTAS 128       // 16 g-tiles x 8 k-chunks, co-resident on 148 SMs

// ---------------- device-global scratch ----------------
__device__ float g_xproj[(size_t)SEQ * GATES * BATCH];   // [t][g][b]
__device__ float g_h[2][BATCH * HIDD];                   // double-buffered h [b][k]
__device__ float g_C[HIDD * BATCH];                      // cell state, idx=j*64+b
__device__ float g_part[8][GATES * BATCH];               // K-split partials [kc][g][b]
__device__ unsigned g_cnt0[8];                           // per-group barrier counters
__device__ unsigned g_cnt1;                              // master counter
__device__ volatile unsigned g_sense;                    // barrier release epoch

// ---------------- init ----------------
__global__ void k_init() {
    int i = blockIdx.x * 256 + threadIdx.x;
    if (i < BATCH * HIDD) {
        g_h[0][i] = 0.0f;
        g_C[i]    = 0.0f;
    }
    if (i < 8) g_cnt0[i] = 0;
    if (i == 0) { g_cnt1 = 0; g_sense = 0; }
}

// ---------------- two-level grid barrier (monotone epochs, no resets) ------
// 8 groups x 16 CTAs. One atomic per CTA on its group counter; group leader
// bumps master; last group leader sets sense. One poller/CTA on one address.
__device__ __forceinline__ void gbar(int grp, unsigned phase) {
    __syncthreads();
    if (threadIdx.x == 0) {
        __threadfence();
        unsigned v = atomicAdd(&g_cnt0[grp], 1u) + 1u;
        if (v == 16u * phase) {
            unsigned w = atomicAdd(&g_cnt1, 1u) + 1u;
            if (w == 8u * phase) {
                __threadfence();
                g_sense = phase;
            } else {
                while (g_sense < phase) { }
            }
        } else {
            while (g_sense < phase) { }
        }
        __threadfence();
    }
    __syncthreads();
}

// ---------------- Kernel 1: Xproj[t][g][b] = emb[x[b,t]] . Wx[g] + bias[g] --
__global__ __launch_bounds__(256) void k_xproj(const int* __restrict__ x,
                                               const float* __restrict__ emb,
                                               const float* __restrict__ W,
                                               const float* __restrict__ Wb) {
    const int t  = blockIdx.y;
    const int g0 = blockIdx.x * 64;

    __shared__ float a_s[64][20];   // [b][k]
    __shared__ float w_s[64][20];   // [g][k]
    __shared__ int   tok[64];

    const int tid = threadIdx.x;
    if (tid < 64) tok[tid] = x[tid * SEQ + t];
    __syncthreads();

    const int tx = tid & 15;   // -> b group
    const int ty = tid >> 4;   // -> g group

    float acc[4][4];            // [gi][bi]
#pragma unroll
    for (int i = 0; i < 4; i++)
#pragma unroll
        for (int j = 0; j < 4; j++) acc[i][j] = 0.0f;

    const int lr = tid >> 2;          // row 0..63
    const int lk = (tid & 3) * 4;     // 0,4,8,12

    for (int k0 = 0; k0 < EMBD; k0 += 16) {
        float4 av = *(const float4*)&emb[(size_t)tok[lr] * EMBD + k0 + lk];
        float4 wv = *(const float4*)&W[(size_t)(g0 + lr) * WROW + k0 + lk];
        *(float4*)&a_s[lr][lk] = av;
        *(float4*)&w_s[lr][lk] = wv;
        __syncthreads();

#pragma unroll
        for (int k = 0; k < 16; k += 4) {
            float4 af[4], wf[4];
#pragma unroll
            for (int i = 0; i < 4; i++) af[i] = *(const float4*)&a_s[tx * 4 + i][k];
#pragma unroll
            for (int i = 0; i < 4; i++) wf[i] = *(const float4*)&w_s[ty * 4 + i][k];
#pragma unroll
            for (int gi = 0; gi < 4; gi++)
#pragma unroll
                for (int bi = 0; bi < 4; bi++) {
                    acc[gi][bi] += af[bi].x * wf[gi].x;
                    acc[gi][bi] += af[bi].y * wf[gi].y;
                    acc[gi][bi] += af[bi].z * wf[gi].z;
                    acc[gi][bi] += af[bi].w * wf[gi].w;
                }
        }
        __syncthreads();
    }

#pragma unroll
    for (int gi = 0; gi < 4; gi++) {
        int g = g0 + ty * 4 + gi;
        float bias = Wb[g];
        float4 v;
        v.x = acc[gi][0] + bias;
        v.y = acc[gi][1] + bias;
        v.z = acc[gi][2] + bias;
        v.w = acc[gi][3] + bias;
        *(float4*)&g_xproj[((size_t)t * GATES + g) * BATCH + tx * 4] = v;
    }
}

// ---------------- Kernel 2: persistent recurrence ---------------------------
// 128 CTAs: gt = bx&15 (128-gate tile), kc = bx>>4 (64-k chunk).
// Thread tile 8g x 4b (FMA-bound). Wh tile (128g x 64k, 32KB) resident.
// h staged transposed [k][b] (conflict-free). Two cheap barriers per step.
__global__ __launch_bounds__(256) void k_recur(const float* __restrict__ W) {
    const int bx = blockIdx.x;
    const int gt = bx & 15;
    const int kc = bx >> 4;
    const int g0 = gt * 128;
    const int kbase = kc * 64;

    __shared__ float w_s[128][64];   // [g][k] resident Wh tile, 32KB
    __shared__ float h_s[32][68];    // [k][b] stage (transposed), pad 68
    __shared__ float hs2[256];       // elem output transpose buffer

    const int tid = threadIdx.x;
    const int tx = tid & 15;         // -> b group (4 b)
    const int ty = tid >> 4;         // -> g group (8 g)

    // elementwise ownership: idx = bx*256 + tid -> (j, b)
    const int idx = bx * 256 + tid;
    const int ej  = idx >> 6;
    const int eb  = idx & 63;

    // Preload Wh tile once: 128 rows x 64 k = 2048 float4, 8 per thread
#pragma unroll
    for (int i = 0; i < 8; i++) {
        int lin = tid + i * 256;     // float4 slot 0..2047
        int r   = lin >> 4;          // row 0..127
        int kq  = (lin & 15) * 4;    // 0..60
        *(float4*)&w_s[r][kq] =
            *(const float4*)&W[(size_t)(g0 + r) * WROW + EMBD + kbase + kq];
    }
    __syncthreads();

    unsigned phase = 0;

    for (int t = 0; t < SEQ; t++) {
        const float* __restrict__ h = g_h[t & 1];

        float acc[8][4];
#pragma unroll
        for (int i = 0; i < 8; i++)
#pragma unroll
            for (int j = 0; j < 4; j++) acc[i][j] = 0.0f;

        for (int kk = 0; kk < 64; kk += 32) {
            // stage 64b x 32k transposed: 512 float4 loads, 2 per thread
#pragma unroll
            for (int i = 0; i < 2; i++) {
                int lin = tid + i * 256;       // 0..511
                int b   = lin >> 3;            // 0..63
                int k4  = lin & 7;             // 0..7
                float4 v = *(const float4*)&h[b * HIDD + kbase + kk + k4 * 4];
                h_s[k4 * 4 + 0][b] = v.x;
                h_s[k4 * 4 + 1][b] = v.y;
                h_s[k4 * 4 + 2][b] = v.z;
                h_s[k4 * 4 + 3][b] = v.w;
            }
            __syncthreads();

#pragma unroll
            for (int k4 = 0; k4 < 8; k4++) {
                float4 wf[8];
#pragma unroll
                for (int gi = 0; gi < 8; gi++)
                    wf[gi] = *(const float4*)&w_s[ty * 8 + gi][kk + k4 * 4];
#pragma unroll
                for (int kkk = 0; kkk < 4; kkk++) {
                    float4 hb = *(const float4*)&h_s[k4 * 4 + kkk][tx * 4];
#pragma unroll
                    for (int gi = 0; gi < 8; gi++) {
                        float wv = (kkk == 0) ? wf[gi].x :
                                   (kkk == 1) ? wf[gi].y :
                                   (kkk == 2) ? wf[gi].z : wf[gi].w;
                        acc[gi][0] += wv * hb.x;
                        acc[gi][1] += wv * hb.y;
                        acc[gi][2] += wv * hb.z;
                        acc[gi][3] += wv * hb.w;
                    }
                }
            }
            __syncthreads();
        }

        // write partials [kc][g][b]
#pragma unroll
        for (int gi = 0; gi < 8; gi++) {
            int g = g0 + ty * 8 + gi;
            float4 v;
            v.x = acc[gi][0]; v.y = acc[gi][1]; v.z = acc[gi][2]; v.w = acc[gi][3];
            *(float4*)&g_part[kc][g * BATCH + tx * 4] = v;
        }
        __threadfence();

        // prefetch step-local elem inputs (independent of other CTAs)
        float xp[4];
#pragma unroll
        for (int q = 0; q < 4; q++)
            xp[q] = g_xproj[((size_t)t * GATES + (q * HIDD + ej)) * BATCH + eb];
        float Cold = g_C[idx];

        gbar(kc, ++phase);   // all partials visible

        // ---- elementwise LSTM cell ----
        float hval;
        {
            float v[4];
#pragma unroll
            for (int q = 0; q < 4; q++) {
                int g = q * HIDD + ej;
                float s = xp[q];
#pragma unroll
                for (int c = 0; c < 8; c++) s += g_part[c][g * BATCH + eb];
                v[q] = s;
            }

            float f  = 1.0f / (1.0f + expf(-v[0]));
            float ig = 1.0f / (1.0f + expf(-v[1]));
            float o  = 1.0f / (1.0f + expf(-v[2]));
            float ct = tanhf(v[3]);

            float C = f * Cold + ig * ct;
            g_C[idx] = C;
            hval = o * tanhf(C);
        }

        // transpose h through smem -> float4 stores into [b][j] layout
        hs2[tid] = hval;                 // hs2[jl*64 + b]
        __syncthreads();
        if (tid < 64) {
            float4 o4;
            o4.x = hs2[tid];
            o4.y = hs2[64 + tid];
            o4.z = hs2[128 + tid];
            o4.w = hs2[192 + tid];
            *(float4*)&g_h[(t + 1) & 1][tid * HIDD + bx * 4] = o4;
        }
        __threadfence();

        gbar(kc, ++phase);   // new h visible before next step
    }
}

// ---------------- Kernel 4: FC head  out[b][n] = h[b].fc[n] + bias ----------
__global__ __launch_bounds__(256) void k_fc(const float* __restrict__ fcw,
                                            const float* __restrict__ fcb,
                                            float* __restrict__ out) {
    const int n0 = blockIdx.x * 64;
    const float* __restrict__ h = g_h[0];   // t=511 wrote buffer (512&1)=0

    __shared__ float h_s[64][68];   // [b][k]
    __shared__ float w_s[64][68];   // [n][k]

    const int tid = threadIdx.x;
    const int tx = tid & 15;        // -> n group
    const int ty = tid >> 4;        // -> b group

    float acc[4][4];                // [bi][ni]
#pragma unroll
    for (int i = 0; i < 4; i++)
#pragma unroll
        for (int j = 0; j < 4; j++) acc[i][j] = 0.0f;

    for (int k0 = 0; k0 < HIDD; k0 += 64) {
#pragma unroll
        for (int i = 0; i < 4; i++) {
            int lin = tid + i * 256;
            int r   = lin >> 4;
            int kq  = (lin & 15) * 4;
            *(float4*)&h_s[r][kq] = *(const float4*)&h[r * HIDD + k0 + kq];
            int n = n0 + r;
            float4 wv = make_float4(0.f, 0.f, 0.f, 0.f);
            if (n < NCLS) wv = *(const float4*)&fcw[(size_t)n * HIDD + k0 + kq];
            *(float4*)&w_s[r][kq] = wv;
        }
        __syncthreads();

#pragma unroll
        for (int k = 0; k < 64; k += 4) {
            float4 hf[4], wf[4];
#pragma unroll
            for (int i = 0; i < 4; i++) hf[i] = *(const float4*)&h_s[ty * 4 + i][k];
#pragma unroll
            for (int i = 0; i < 4; i++) wf[i] = *(const float4*)&w_s[tx * 4 + i][k];
#pragma unroll
            for (int bi = 0; bi < 4; bi++)
#pragma unroll
                for (int ni = 0; ni < 4; ni++) {
                    acc[bi][ni] += hf[bi].x * wf[ni].x;
                    acc[bi][ni] += hf[bi].y * wf[ni].y;
                    acc[bi][ni] += hf[bi].z * wf[ni].z;
                    acc[bi][ni] += hf[bi].w * wf[ni].w;
                }
        }
        __syncthreads();
    }

#pragma unroll
    for (int bi = 0; bi < 4; bi++) {
        int b = ty * 4 + bi;
#pragma unroll
        for (int ni = 0; ni < 4; ni++) {
            int n = n0 + tx * 4 + ni;
            if (n < NCLS) out[(size_t)b * NCLS + n] = acc[bi][ni] + fcb[n];
        }
    }
}

// ---------------- launch ----------------
extern "C" void kernel_launch(void* const* d_in, const int* in_sizes, int n_in,
                              void* d_out, int out_size) {
    const int*   x   = (const int*)  d_in[0];
    const float* emb = (const float*)d_in[1];
    const float* W   = (const float*)d_in[2];
    const float* Wb  = (const float*)d_in[3];
    const float* fcw = (const float*)d_in[4];
    const float* fcb = (const float*)d_in[5];
    float* out = (float*)d_out;

    k_init<<<(BATCH * HIDD + 255) / 256, 256>>>();
    k_xproj<<<dim3(32, SEQ), 256>>>(x, emb, W, Wb);
    k_recur<<<RCTAS, 256>>>(W);
    k_fc<<<(NCLS + 63) / 64, 256>>>(fcw, fcb, out);
}

// round 7
// speedup vs baseline: 3.3071x; 1.2793x over previous
#include <cuda_runtime.h>
#include <math.h>

#define BATCH 64
#define SEQ   512
#define EMBD  256
#define HIDD  512
#define GATES 2048      // 4*HIDD
#define WROW  768       // EMB + HID
#define NCLS  50257
#define RCTAS 128       // 16 g-tiles x 8 k-chunks, co-resident

// ---------------- device-global scratch ----------------
__device__ float g_xproj[(size_t)SEQ * GATES * BATCH];   // [t][g][b]
__device__ float g_h[2][BATCH * HIDD];                   // double-buffered h [b][k]
__device__ float g_C[HIDD * BATCH];                      // cell state, idx=j*64+b
__device__ float g_part[8][GATES * BATCH];               // K-split partials [kc][g][b]
struct PadCnt { unsigned c; unsigned pad[31]; };         // 128B line per counter
__device__ PadCnt g_cnt0[8];
__device__ unsigned g_cnt1;
__device__ volatile unsigned g_sense;

__device__ __forceinline__ float fast_tanh(float x) {
    float r;
    asm("tanh.approx.f32 %0, %1;" : "=f"(r) : "f"(x));
    return r;
}
__device__ __forceinline__ float fast_sigmoid(float x) {
    return 0.5f + 0.5f * fast_tanh(0.5f * x);
}

// ---------------- init ----------------
__global__ void k_init() {
    int i = blockIdx.x * 256 + threadIdx.x;
    if (i < BATCH * HIDD) {
        g_h[0][i] = 0.0f;
        g_C[i]    = 0.0f;
    }
    if (i < 8) g_cnt0[i].c = 0;
    if (i == 0) { g_cnt1 = 0; g_sense = 0; }
}

// ---------------- two-level grid barrier (monotone epochs) ------------------
__device__ __forceinline__ void gbar(int grp, unsigned phase) {
    __syncthreads();
    if (threadIdx.x == 0) {
        __threadfence();                    // release
        unsigned v = atomicAdd(&g_cnt0[grp].c, 1u) + 1u;
        if (v == 16u * phase) {
            unsigned w = atomicAdd(&g_cnt1, 1u) + 1u;
            if (w == 8u * phase) {
                __threadfence();
                g_sense = phase;
            } else {
                while (g_sense < phase) { }
            }
        } else {
            while (g_sense < phase) { }
        }
        __threadfence();                    // acquire
    }
    __syncthreads();
}

// ---------------- Kernel 1: Xproj[t][g][b] = emb[x[b,t]] . Wx[g] + bias[g] --
// Grid (32 g-tiles, 512 t), 128 threads. BK=32, microtile 8g x 4b (FMA-bound).
__global__ __launch_bounds__(128) void k_xproj(const int* __restrict__ x,
                                               const float* __restrict__ emb,
                                               const float* __restrict__ W,
                                               const float* __restrict__ Wb) {
    const int t  = blockIdx.y;
    const int g0 = blockIdx.x * 64;

    __shared__ float a_s[64][36];   // [b][k] 32-k stage
    __shared__ float w_s[64][36];   // [g][k]
    __shared__ int   tok[64];

    const int tid = threadIdx.x;
    if (tid < 64) tok[tid] = x[tid * SEQ + t];
    __syncthreads();

    const int tx = tid & 15;   // -> 4 b
    const int ty = tid >> 4;   // -> 8 g (0..7)

    float acc[8][4];            // [gi][bi]
#pragma unroll
    for (int i = 0; i < 8; i++)
#pragma unroll
        for (int j = 0; j < 4; j++) acc[i][j] = 0.0f;

    for (int k0 = 0; k0 < EMBD; k0 += 32) {
        // stage 64x32 of A and W: 512 float4 each, 4 per thread each
#pragma unroll
        for (int i = 0; i < 4; i++) {
            int lin = tid + i * 128;          // 0..511
            int r   = lin >> 3;               // 0..63
            int kq  = (lin & 7) * 4;          // 0..28
            *(float4*)&a_s[r][kq] = *(const float4*)&emb[(size_t)tok[r] * EMBD + k0 + kq];
            *(float4*)&w_s[r][kq] = *(const float4*)&W[(size_t)(g0 + r) * WROW + k0 + kq];
        }
        __syncthreads();

#pragma unroll
        for (int k4 = 0; k4 < 8; k4++) {
            float4 af[4], wf[8];
#pragma unroll
            for (int i = 0; i < 4; i++) af[i] = *(const float4*)&a_s[tx * 4 + i][k4 * 4];
#pragma unroll
            for (int i = 0; i < 8; i++) wf[i] = *(const float4*)&w_s[ty * 8 + i][k4 * 4];
#pragma unroll
            for (int gi = 0; gi < 8; gi++)
#pragma unroll
                for (int bi = 0; bi < 4; bi++) {
                    acc[gi][bi] += wf[gi].x * af[bi].x;
                    acc[gi][bi] += wf[gi].y * af[bi].y;
                    acc[gi][bi] += wf[gi].z * af[bi].z;
                    acc[gi][bi] += wf[gi].w * af[bi].w;
                }
        }
        __syncthreads();
    }

#pragma unroll
    for (int gi = 0; gi < 8; gi++) {
        int g = g0 + ty * 8 + gi;
        float bias = Wb[g];
        float4 v;
        v.x = acc[gi][0] + bias;
        v.y = acc[gi][1] + bias;
        v.z = acc[gi][2] + bias;
        v.w = acc[gi][3] + bias;
        *(float4*)&g_xproj[((size_t)t * GATES + g) * BATCH + tx * 4] = v;
    }
}

// ---------------- Kernel 2: persistent recurrence ---------------------------
// 128 CTAs: gt = bx&15 (128-gate tile), kc = bx>>4 (64-k chunk).
// 8g x 4b microtile; Wh tile resident; h stage 2 via register prefetch.
__global__ __launch_bounds__(256) void k_recur(const float* __restrict__ W) {
    const int bx = blockIdx.x;
    const int gt = bx & 15;
    const int kc = bx >> 4;
    const int g0 = gt * 128;
    const int kbase = kc * 64;

    __shared__ float w_s[128][64];   // [g][k] resident Wh tile, 32KB
    __shared__ float h_s[32][68];    // [k][b] transposed stage
    __shared__ float hs2[256];       // elem output transpose buffer

    const int tid = threadIdx.x;
    const int tx = tid & 15;         // -> 4 b
    const int ty = tid >> 4;         // -> 8 g

    const int idx = bx * 256 + tid;  // elem ownership
    const int ej  = idx >> 6;
    const int eb  = idx & 63;

    // stage-loader coords (2 float4 per thread per 32-k stage)
    const int lb0 = tid >> 3,          lk0 = (tid & 7) * 4;
    const int lb1 = (tid + 256) >> 3,  lk1 = ((tid + 256) & 7) * 4;

    // Preload Wh tile once
#pragma unroll
    for (int i = 0; i < 8; i++) {
        int lin = tid + i * 256;
        int r   = lin >> 4;
        int kq  = (lin & 15) * 4;
        *(float4*)&w_s[r][kq] =
            *(const float4*)&W[(size_t)(g0 + r) * WROW + EMBD + kbase + kq];
    }
    __syncthreads();

    unsigned phase = 0;

    for (int t = 0; t < SEQ; t++) {
        const float* __restrict__ h = g_h[t & 1];

        float acc[8][4];
#pragma unroll
        for (int i = 0; i < 8; i++)
#pragma unroll
            for (int j = 0; j < 4; j++) acc[i][j] = 0.0f;

        // ---- stage 0 load + store ----
        float4 p0 = *(const float4*)&h[lb0 * HIDD + kbase + lk0];
        float4 p1 = *(const float4*)&h[lb1 * HIDD + kbase + lk1];
        h_s[lk0 + 0][lb0] = p0.x; h_s[lk0 + 1][lb0] = p0.y;
        h_s[lk0 + 2][lb0] = p0.z; h_s[lk0 + 3][lb0] = p0.w;
        h_s[lk1 + 0][lb1] = p1.x; h_s[lk1 + 1][lb1] = p1.y;
        h_s[lk1 + 2][lb1] = p1.z; h_s[lk1 + 3][lb1] = p1.w;
        __syncthreads();

        // ---- prefetch stage 1 into registers ----
        float4 q0 = *(const float4*)&h[lb0 * HIDD + kbase + 32 + lk0];
        float4 q1 = *(const float4*)&h[lb1 * HIDD + kbase + 32 + lk1];

        // ---- compute stage 0 (k = 0..31 of w_s) ----
#pragma unroll
        for (int k4 = 0; k4 < 8; k4++) {
            float4 wf[8];
#pragma unroll
            for (int gi = 0; gi < 8; gi++)
                wf[gi] = *(const float4*)&w_s[ty * 8 + gi][k4 * 4];
#pragma unroll
            for (int kkk = 0; kkk < 4; kkk++) {
                float4 hb = *(const float4*)&h_s[k4 * 4 + kkk][tx * 4];
#pragma unroll
                for (int gi = 0; gi < 8; gi++) {
                    float wv = (kkk == 0) ? wf[gi].x :
                               (kkk == 1) ? wf[gi].y :
                               (kkk == 2) ? wf[gi].z : wf[gi].w;
                    acc[gi][0] += wv * hb.x;
                    acc[gi][1] += wv * hb.y;
                    acc[gi][2] += wv * hb.z;
                    acc[gi][3] += wv * hb.w;
                }
            }
        }
        __syncthreads();

        // ---- store stage 1 ----
        h_s[lk0 + 0][lb0] = q0.x; h_s[lk0 + 1][lb0] = q0.y;
        h_s[lk0 + 2][lb0] = q0.z; h_s[lk0 + 3][lb0] = q0.w;
        h_s[lk1 + 0][lb1] = q1.x; h_s[lk1 + 1][lb1] = q1.y;
        h_s[lk1 + 2][lb1] = q1.z; h_s[lk1 + 3][lb1] = q1.w;
        __syncthreads();

        // ---- compute stage 1 (k = 32..63 of w_s) ----
#pragma unroll
        for (int k4 = 0; k4 < 8; k4++) {
            float4 wf[8];
#pragma unroll
            for (int gi = 0; gi < 8; gi++)
                wf[gi] = *(const float4*)&w_s[ty * 8 + gi][32 + k4 * 4];
#pragma unroll
            for (int kkk = 0; kkk < 4; kkk++) {
                float4 hb = *(const float4*)&h_s[k4 * 4 + kkk][tx * 4];
#pragma unroll
                for (int gi = 0; gi < 8; gi++) {
                    float wv = (kkk == 0) ? wf[gi].x :
                               (kkk == 1) ? wf[gi].y :
                               (kkk == 2) ? wf[gi].z : wf[gi].w;
                    acc[gi][0] += wv * hb.x;
                    acc[gi][1] += wv * hb.y;
                    acc[gi][2] += wv * hb.z;
                    acc[gi][3] += wv * hb.w;
                }
            }
        }

        // write partials [kc][g][b]
#pragma unroll
        for (int gi = 0; gi < 8; gi++) {
            int g = g0 + ty * 8 + gi;
            float4 v;
            v.x = acc[gi][0]; v.y = acc[gi][1]; v.z = acc[gi][2]; v.w = acc[gi][3];
            *(float4*)&g_part[kc][g * BATCH + tx * 4] = v;
        }

        // prefetch step-local elem inputs
        float xp[4];
#pragma unroll
        for (int q = 0; q < 4; q++)
            xp[q] = g_xproj[((size_t)t * GATES + (q * HIDD + ej)) * BATCH + eb];
        float Cold = g_C[idx];

        gbar(kc, ++phase);   // all partials visible (fence inside)

        // ---- elementwise LSTM cell ----
        float hval;
        {
            float v[4];
#pragma unroll
            for (int q = 0; q < 4; q++) {
                int g = q * HIDD + ej;
                float s = xp[q];
#pragma unroll
                for (int c = 0; c < 8; c++) s += g_part[c][g * BATCH + eb];
                v[q] = s;
            }
            float f  = fast_sigmoid(v[0]);
            float ig = fast_sigmoid(v[1]);
            float o  = fast_sigmoid(v[2]);
            float ct = fast_tanh(v[3]);
            float C = f * Cold + ig * ct;
            g_C[idx] = C;
            hval = o * fast_tanh(C);
        }

        // transpose h through smem -> float4 stores into [b][j]
        hs2[tid] = hval;                 // hs2[jl*64 + b]
        __syncthreads();
        if (tid < 64) {
            float4 o4;
            o4.x = hs2[tid];
            o4.y = hs2[64 + tid];
            o4.z = hs2[128 + tid];
            o4.w = hs2[192 + tid];
            *(float4*)&g_h[(t + 1) & 1][tid * HIDD + bx * 4] = o4;
        }

        gbar(kc, ++phase);   // new h visible before next step (fence inside)
    }
}

// ---------------- Kernel 4: FC head  out[b][n] = h[b].fc[n] + bias ----------
// BN=128, BK=32 stage, 256 threads, microtile 8n x 4b (FMA-bound).
__global__ __launch_bounds__(256) void k_fc(const float* __restrict__ fcw,
                                            const float* __restrict__ fcb,
                                            float* __restrict__ out) {
    const int n0 = blockIdx.x * 128;
    const float* __restrict__ h = g_h[0];

    __shared__ float h_s[64][36];    // [b][k]
    __shared__ float w_s[128][36];   // [n][k]

    const int tid = threadIdx.x;
    const int tx = tid & 15;         // -> 4 b
    const int ty = tid >> 4;         // -> 8 n

    float acc[8][4];                 // [ni][bi]
#pragma unroll
    for (int i = 0; i < 8; i++)
#pragma unroll
        for (int j = 0; j < 4; j++) acc[i][j] = 0.0f;

    for (int k0 = 0; k0 < HIDD; k0 += 32) {
        // h: 64x32 = 512 float4 -> 2 per thread; w: 128x32 = 1024 float4 -> 4
#pragma unroll
        for (int i = 0; i < 2; i++) {
            int lin = tid + i * 256;
            int r   = lin >> 3;
            int kq  = (lin & 7) * 4;
            *(float4*)&h_s[r][kq] = *(const float4*)&h[r * HIDD + k0 + kq];
        }
#pragma unroll
        for (int i = 0; i < 4; i++) {
            int lin = tid + i * 256;
            int r   = lin >> 3;
            int kq  = (lin & 7) * 4;
            int n = n0 + r;
            float4 wv = make_float4(0.f, 0.f, 0.f, 0.f);
            if (n < NCLS) wv = *(const float4*)&fcw[(size_t)n * HIDD + k0 + kq];
            *(float4*)&w_s[r][kq] = wv;
        }
        __syncthreads();

#pragma unroll
        for (int k4 = 0; k4 < 8; k4++) {
            float4 hf[4], wf[8];
#pragma unroll
            for (int i = 0; i < 4; i++) hf[i] = *(const float4*)&h_s[tx * 4 + i][k4 * 4];
#pragma unroll
            for (int i = 0; i < 8; i++) wf[i] = *(const float4*)&w_s[ty * 8 + i][k4 * 4];
#pragma unroll
            for (int ni = 0; ni < 8; ni++)
#pragma unroll
                for (int bi = 0; bi < 4; bi++) {
                    acc[ni][bi] += wf[ni].x * hf[bi].x;
                    acc[ni][bi] += wf[ni].y * hf[bi].y;
                    acc[ni][bi] += wf[ni].z * hf[bi].z;
                    acc[ni][bi] += wf[ni].w * hf[bi].w;
                }
        }
        __syncthreads();
    }

#pragma unroll
    for (int ni = 0; ni < 8; ni++) {
        int n = n0 + ty * 8 + ni;
        if (n < NCLS) {
            float bias = fcb[n];
#pragma unroll
            for (int bi = 0; bi < 4; bi++) {
                int b = tx * 4 + bi;
                out[(size_t)b * NCLS + n] = acc[ni][bi] + bias;
            }
        }
    }
}

// ---------------- launch ----------------
extern "C" void kernel_launch(void* const* d_in, const int* in_sizes, int n_in,
                              void* d_out, int out_size) {
    const int*   x   = (const int*)  d_in[0];
    const float* emb = (const float*)d_in[1];
    const float* W   = (const float*)d_in[2];
    const float* Wb  = (const float*)d_in[3];
    const float* fcw = (const float*)d_in[4];
    const float* fcb = (const float*)d_in[5];
    float* out = (float*)d_out;

    k_init<<<(BATCH * HIDD + 255) / 256, 256>>>();
    k_xproj<<<dim3(32, SEQ), 128>>>(x, emb, W, Wb);
    k_recur<<<RCTAS, 256>>>(W);
    k_fc<<<(NCLS + 127) / 128, 256>>>(fcw, fcb, out);
}